// round 13
// baseline (speedup 1.0000x reference)
#include <cuda_runtime.h>
#include <cuda_fp16.h>
#include <cstdint>
#include <math.h>

#define BB   4
#define SS   2048
#define DD   1024
#define HH   16
#define HDIM 64
#define MM   (BB*SS)          // 8192

#define NEG_BIG (-1e30f)

// Scratch (device globals)
__device__ __half g_xn[MM*DD];        // LN output, fp16
__device__ __half g_q [MM*DD];        // [B,H,S,Hd]
__device__ __half g_k [MM*DD];        // [B,H,S,Hd]
__device__ __half g_v [MM*DD];        // [B,H,Hd,S]  (head-transposed)
__device__ __half g_ao[MM*DD];        // [B,S,D]
__device__ __half g_wt[4*DD*DD];      // fp16 weights (q,k,v,o contiguous)
__device__ float  g_bias[3*DD];       // combined qkv bias

__device__ __forceinline__ uint32_t smem_u32(const void* p) {
    uint32_t a;
    asm("{ .reg .u64 t; cvta.to.shared.u64 t, %1; cvt.u32.u64 %0, t; }" : "=r"(a) : "l"(p));
    return a;
}
#define CP_ASYNC16(dst, src) \
    asm volatile("cp.async.cg.shared.global [%0], [%1], 16;" :: "r"(dst), "l"(src))
#define CP_COMMIT() asm volatile("cp.async.commit_group;" ::: "memory")
#define CP_WAIT1()  asm volatile("cp.async.wait_group 1;" ::: "memory")
#define CP_WAIT0()  asm volatile("cp.async.wait_group 0;" ::: "memory")

__device__ __forceinline__ void mma_f16(float& c0, float& c1, float& c2, float& c3,
                                        uint32_t a0, uint32_t a1, uint32_t a2, uint32_t a3,
                                        uint32_t b0, uint32_t b1) {
    asm volatile(
        "mma.sync.aligned.m16n8k16.row.col.f32.f16.f16.f32 "
        "{%0,%1,%2,%3}, {%4,%5,%6,%7}, {%8,%9}, {%0,%1,%2,%3};"
        : "+f"(c0), "+f"(c1), "+f"(c2), "+f"(c3)
        : "r"(a0), "r"(a1), "r"(a2), "r"(a3), "r"(b0), "r"(b1));
}
__device__ __forceinline__ void ldsm4(uint32_t& r0, uint32_t& r1, uint32_t& r2, uint32_t& r3,
                                      uint32_t a) {
    asm volatile("ldmatrix.sync.aligned.m8n8.x4.shared.b16 {%0,%1,%2,%3}, [%4];"
                 : "=r"(r0), "=r"(r1), "=r"(r2), "=r"(r3) : "r"(a));
}

// ---------------------------------------------------------------------------
// Prep kernels
// ---------------------------------------------------------------------------
__global__ __launch_bounds__(256) void cvtw_all(
    const float* __restrict__ w0, const float* __restrict__ w1,
    const float* __restrict__ w2, const float* __restrict__ w3)
{
    int widx = blockIdx.y;
    const float* w = (widx == 0) ? w0 : (widx == 1) ? w1 : (widx == 2) ? w2 : w3;
    int i = blockIdx.x * 256 + threadIdx.x;
    float4 v = ((const float4*)w)[i];
    __half2 h01 = __floats2half2_rn(v.x, v.y);
    __half2 h23 = __floats2half2_rn(v.z, v.w);
    uint2 u; u.x = *(uint32_t*)&h01; u.y = *(uint32_t*)&h23;
    ((uint2*)(g_wt + (size_t)widx * DD * DD))[i] = u;
}

__global__ __launch_bounds__(256) void bias_kernel(
    const float* __restrict__ bq, const float* __restrict__ bk, const float* __restrict__ bv)
{
    int i = blockIdx.x * 256 + threadIdx.x;   // 0..3071
    const float* src = (i < DD) ? bq : (i < 2*DD) ? bk : bv;
    g_bias[i] = src[i & (DD-1)];
}

// ---------------------------------------------------------------------------
// LayerNorm: one WARP per row, 8 rows/block.
// ---------------------------------------------------------------------------
__global__ __launch_bounds__(256) void ln_kernel(
    const float* __restrict__ x,
    const float* __restrict__ gamma,
    const float* __restrict__ beta)
{
    int row  = blockIdx.x * 8 + (threadIdx.x >> 5);
    int lane = threadIdx.x & 31;
    const float4* xr = (const float4*)(x + (size_t)row * DD);

    float4 v[8];
    float s = 0.0f;
    #pragma unroll
    for (int i = 0; i < 8; i++) {
        v[i] = xr[lane + 32*i];
        s += v[i].x + v[i].y + v[i].z + v[i].w;
    }
    #pragma unroll
    for (int o = 16; o > 0; o >>= 1) s += __shfl_xor_sync(0xffffffffu, s, o);
    float mean = s * (1.0f / DD);

    float s2 = 0.0f;
    #pragma unroll
    for (int i = 0; i < 8; i++) {
        v[i].x -= mean; v[i].y -= mean; v[i].z -= mean; v[i].w -= mean;
        s2 += v[i].x*v[i].x + v[i].y*v[i].y + v[i].z*v[i].z + v[i].w*v[i].w;
    }
    #pragma unroll
    for (int o = 16; o > 0; o >>= 1) s2 += __shfl_xor_sync(0xffffffffu, s2, o);
    float rstd = rsqrtf(s2 * (1.0f / DD) + 1e-5f);

    uint2* dst = (uint2*)(g_xn + (size_t)row * DD);
    #pragma unroll
    for (int i = 0; i < 8; i++) {
        float4 g  = ((const float4*)gamma)[lane + 32*i];
        float4 bb = ((const float4*)beta)[lane + 32*i];
        __half2 h01 = __floats2half2_rn(v[i].x * rstd * g.x + bb.x, v[i].y * rstd * g.y + bb.y);
        __half2 h23 = __floats2half2_rn(v[i].z * rstd * g.z + bb.z, v[i].w * rstd * g.w + bb.w);
        uint2 u; u.x = *(uint32_t*)&h01; u.y = *(uint32_t*)&h23;
        dst[lane + 32*i] = u;
    }
}

// ---------------------------------------------------------------------------
// fp16 tensor GEMM: 128x64 tile, BK=32, 3-stage cp.async ring, 3 CTAs/SM.
// 8 warps in 4m x 2n grid, warp tile 32x32 (acc = 32 regs).
// mode 0: fused QKV (V block-columns transposed via smem -> coalesced stores)
// mode 1: output GEMM (+bias,+resid, fp32 out)
// ---------------------------------------------------------------------------
#define KPG 20
#define A_WORDS (128 * KPG)                 // 2560 words
#define STG_WORDS ((128 + 64) * KPG)        // 3840 words per stage
#define GSTG 3
#define GEMM_SMEM_BYTES (GSTG * STG_WORDS * 4)   // 46080

__global__ __launch_bounds__(256, 3) void gemm_h(
    int mode,
    const float* __restrict__ bias_o,
    const float* __restrict__ resid,
    float* __restrict__ out)
{
    extern __shared__ uint32_t smem[];
    const __half* A = mode ? g_ao : g_xn;
    const __half* W = mode ? (g_wt + (size_t)3 * DD * DD) : g_wt;

    int tid = threadIdx.x;
    int wid = tid >> 5, lane = tid & 31;
    int m0 = blockIdx.y * 128;
    int n0 = blockIdx.x * 64;

    int wm = (wid & 3) * 32;        // warp m offset
    int wn = (wid >> 2) * 32;       // warp n offset
    int lr = lane >> 2;
    int lc = lane & 3;

    uint32_t sbase = smem_u32(smem);

    // staging: A = 512 chunks (2/thread), B = 256 chunks (1/thread)
    int arow0 = tid >> 2,         ac0 = tid & 3;          // A chunk 0
    int arow1 = (tid + 256) >> 2, ac1 = (tid + 256) & 3;  // A chunk 1
    int brow  = tid >> 2,         bc  = tid & 3;          // B chunk
    uint32_t sA0 = sbase + (arow0 * KPG + ac0 * 4) * 4;
    uint32_t sA1 = sbase + (arow1 * KPG + ac1 * 4) * 4;
    uint32_t sB  = sbase + (A_WORDS + brow * KPG + bc * 4) * 4;
    const __half* gA0 = A + (size_t)(m0 + arow0) * DD + ac0 * 8;
    const __half* gA1 = A + (size_t)(m0 + arow1) * DD + ac1 * 8;
    const __half* gB  = W + (size_t)(n0 + brow) * DD + bc * 8;

    // ldmatrix lane offsets (within a stage)
    uint32_t aoff[2], boff[2];
    #pragma unroll
    for (int tm = 0; tm < 2; tm++)
        aoff[tm] = ((wm + tm * 16 + (lane & 15)) * KPG + ((lane >> 4) << 2)) * 4;
    #pragma unroll
    for (int np = 0; np < 2; np++)
        boff[np] = (A_WORDS +
            (wn + np * 16 + (lane & 7) + ((lane >> 4) << 3)) * KPG + (((lane >> 3) & 1) << 2)) * 4;

    float acc[2][4][4];
    #pragma unroll
    for (int tm = 0; tm < 2; tm++)
        #pragma unroll
        for (int tn = 0; tn < 4; tn++)
            #pragma unroll
            for (int c = 0; c < 4; c++) acc[tm][tn][c] = 0.0f;

    // prologue: stages 0,1
    #pragma unroll
    for (int s = 0; s < 2; s++) {
        uint32_t so = s * STG_WORDS * 4;
        CP_ASYNC16(sA0 + so, gA0 + s * 32);
        CP_ASYNC16(sA1 + so, gA1 + s * 32);
        CP_ASYNC16(sB  + so, gB  + s * 32);
        CP_COMMIT();
    }

    int stg = 0;
    for (int kt = 0; kt < 32; kt++) {
        CP_WAIT1();
        __syncthreads();

        if (kt + 2 < 32) {
            int ns = stg + 2; if (ns >= GSTG) ns -= GSTG;
            uint32_t so = ns * STG_WORDS * 4;
            int k0n = (kt + 2) * 32;
            CP_ASYNC16(sA0 + so, gA0 + k0n);
            CP_ASYNC16(sA1 + so, gA1 + k0n);
            CP_ASYNC16(sB  + so, gB  + k0n);
        }
        CP_COMMIT();

        uint32_t bb = sbase + stg * STG_WORDS * 4;
        #pragma unroll
        for (int ks = 0; ks < 2; ks++) {
            uint32_t kb = ks * 32;    // 16 halfs = 8 words = 32 bytes
            uint32_t a0,a1,a2,a3, c0,c1,c2,c3;
            ldsm4(a0, a1, a2, a3, bb + aoff[0] + kb);
            ldsm4(c0, c1, c2, c3, bb + aoff[1] + kb);
            #pragma unroll
            for (int np = 0; np < 2; np++) {
                uint32_t b0, b1, b2, b3;
                ldsm4(b0, b1, b2, b3, bb + boff[np] + kb);
                mma_f16(acc[0][2*np][0], acc[0][2*np][1], acc[0][2*np][2], acc[0][2*np][3],
                        a0, a1, a2, a3, b0, b1);
                mma_f16(acc[0][2*np+1][0], acc[0][2*np+1][1], acc[0][2*np+1][2], acc[0][2*np+1][3],
                        a0, a1, a2, a3, b2, b3);
                mma_f16(acc[1][2*np][0], acc[1][2*np][1], acc[1][2*np][2], acc[1][2*np][3],
                        c0, c1, c2, c3, b0, b1);
                mma_f16(acc[1][2*np+1][0], acc[1][2*np+1][1], acc[1][2*np+1][2], acc[1][2*np+1][3],
                        c0, c1, c2, c3, b2, b3);
            }
        }
        if (++stg >= GSTG) stg = 0;
    }

    CP_WAIT0();
    __syncthreads();

    int bI = m0 >> 11, s0 = m0 & (SS - 1);

    if (mode == 0) {
        int sel = n0 >> 10;    // 64-col tile fully within q/k/v region
        if (sel < 2) {
            __half* dst0 = (sel == 0) ? g_q : g_k;
            #pragma unroll
            for (int tm = 0; tm < 2; tm++)
                #pragma unroll
                for (int half = 0; half < 2; half++) {
                    int sI = s0 + wm + tm * 16 + lr + half * 8;
                    #pragma unroll
                    for (int tn = 0; tn < 4; tn++) {
                        int n = n0 + wn + tn * 8 + lc * 2;
                        float r0 = acc[tm][tn][half*2+0] + g_bias[n];
                        float r1 = acc[tm][tn][half*2+1] + g_bias[n+1];
                        int nn = n & (DD - 1);
                        int h = nn >> 6, hd = nn & 63;
                        __half2 hv = __floats2half2_rn(r0, r1);
                        size_t idx = ((size_t)(bI * HH + h) * SS + sI) * HDIM + hd;
                        *(__half2*)(dst0 + idx) = hv;
                    }
                }
        } else {
            // V: transpose 128m x 64n tile via smem, coalesced stores along S
            const int TP = 136;             // halfs per sT row
            __half* sT = (__half*)smem;     // 64 rows x TP  (17.4 KB < 46 KB)
            #pragma unroll
            for (int tm = 0; tm < 2; tm++)
                #pragma unroll
                for (int half = 0; half < 2; half++) {
                    int ml = wm + tm * 16 + lr + half * 8;
                    #pragma unroll
                    for (int tn = 0; tn < 4; tn++) {
                        int nl = wn + tn * 8 + lc * 2;
                        int n = n0 + nl;
                        sT[nl * TP + ml]     = __float2half_rn(acc[tm][tn][half*2+0] + g_bias[n]);
                        sT[(nl+1) * TP + ml] = __float2half_rn(acc[tm][tn][half*2+1] + g_bias[n+1]);
                    }
                }
            __syncthreads();
            // 64 n-rows x 16 chunks (8 halfs each, covering 128 m) = 1024 chunks
            #pragma unroll
            for (int j = 0; j < 4; j++) {
                int f = tid + j * 256;     // 0..1023
                int r = f >> 4, c = f & 15;
                uint4 val = *(const uint4*)(sT + r * TP + c * 8);
                int nglob = n0 - 2 * DD + r;
                int h = nglob >> 6, hd = nglob & 63;
                *(uint4*)(g_v + ((size_t)(bI * HH + h) * HDIM + hd) * SS + s0 + c * 8) = val;
            }
        }
    } else {
        #pragma unroll
        for (int tm = 0; tm < 2; tm++)
            #pragma unroll
            for (int half = 0; half < 2; half++) {
                int m = m0 + wm + tm * 16 + lr + half * 8;
                #pragma unroll
                for (int tn = 0; tn < 4; tn++) {
                    int n = n0 + wn + tn * 8 + lc * 2;
                    float2 bz = *(const float2*)(bias_o + n);
                    size_t idx = (size_t)m * DD + n;
                    float2 rv = *(const float2*)(resid + idx);
                    float2 r;
                    r.x = acc[tm][tn][half*2+0] + bz.x + rv.x;
                    r.y = acc[tm][tn][half*2+1] + bz.y + rv.y;
                    *(float2*)(out + idx) = r;
                }
            }
    }
}

// ---------------------------------------------------------------------------
// fp16 tensor-core causal flash attention, 3-stage K/V ring, one sync/iter.
// 128 queries x 64 keys per iter, Hd=64, 8 warps (warp = 16 rows).
// grid: (S/128 = 16, B*H = 64)
// ---------------------------------------------------------------------------
#define KQ 36
#define ASTG 3
#define QS_OFF 0
#define KS_OFF (128*KQ)                     // + stg*64*KQ
#define VT_OFF (KS_OFF + ASTG*64*KQ)        // + stg*64*KQ
#define PS_OFF (VT_OFF + ASTG*64*KQ)
#define MV_OFF (PS_OFF + 128*KQ)            // + stg*64
#define ATTN_WORDS (MV_OFF + ASTG*64)
#define ATTN_SMEM_BYTES (ATTN_WORDS * 4)    // 92928

__global__ __launch_bounds__(256, 2) void attn_h(const float* __restrict__ mask)
{
    extern __shared__ uint32_t sm2[];
    uint32_t sbase = smem_u32(sm2);

    int qb = (int)gridDim.x - 1 - (int)blockIdx.x;   // heavy blocks first
    int bh = blockIdx.y;
    int b = bh >> 4, h = bh & 15;

    const __half* Qg = g_q + ((size_t)bh * SS + qb * 128) * HDIM;
    const __half* Kg = g_k + (size_t)bh * SS * HDIM;
    const __half* Vg = g_v + (size_t)bh * HDIM * SS;   // [d][s]
    const float*  Mg = mask + b * SS;

    int tid = threadIdx.x;
    int wid = tid >> 5, lane = tid & 31;
    int lr = lane >> 2, lc = lane & 3;
    int wm = wid * 16;

    // stage Q
    #pragma unroll
    for (int i = 0; i < 4; i++) {
        int c = tid + i * 256;
        int row = c >> 3, w4 = c & 7;
        uint4 t = *(const uint4*)(Qg + row * HDIM + w4 * 8);
        *(uint4*)((char*)sm2 + (QS_OFF + row * KQ + w4 * 4) * 4) = t;
    }

    uint32_t aq = sbase + (QS_OFF + (wm + (lane & 15)) * KQ + ((lane >> 4) << 2)) * 4;
    uint32_t ap = sbase + (PS_OFF + (wm + (lane & 15)) * KQ + ((lane >> 4) << 2)) * 4;
    uint32_t bk[4];
    #pragma unroll
    for (int np = 0; np < 4; np++)
        bk[np] = ((np * 16 + (lane & 7) + ((lane >> 4) << 3)) * KQ + (((lane >> 3) & 1) << 2)) * 4;

    int stgRow[2], stgW4[2];
    #pragma unroll
    for (int i = 0; i < 2; i++) {
        int c = tid + i * 256;
        stgRow[i] = c >> 3; stgW4[i] = c & 7;
    }

    float of[8][4];
    #pragma unroll
    for (int nt = 0; nt < 8; nt++)
        #pragma unroll
        for (int c = 0; c < 4; c++) of[nt][c] = 0.0f;
    float m0 = NEG_BIG, m1 = NEG_BIG, l0 = 0.0f, l1 = 0.0f;

    int row_g0 = qb * 128 + wm + lr;
    int row_g1 = row_g0 + 8;
    int arow0 = (wm + lr) * KQ;
    int arow1 = (wm + lr + 8) * KQ;
    uint32_t* Ps = sm2 + PS_OFF;

    int jbmax = 2 * qb + 1;

    // prologue: stages for jb=0,1
    #pragma unroll
    for (int s = 0; s < 2; s++) {
        uint32_t ko = (KS_OFF + s * 64 * KQ) * 4;
        uint32_t vo = (VT_OFF + s * 64 * KQ) * 4;
        int koffs = s * 64;
        #pragma unroll
        for (int i = 0; i < 2; i++) {
            CP_ASYNC16(sbase + ko + (stgRow[i] * KQ + stgW4[i] * 4) * 4,
                       Kg + (size_t)(koffs + stgRow[i]) * HDIM + stgW4[i] * 8);
            CP_ASYNC16(sbase + vo + (stgRow[i] * KQ + stgW4[i] * 4) * 4,
                       Vg + (size_t)stgRow[i] * SS + koffs + stgW4[i] * 8);
        }
        if (tid < 16) CP_ASYNC16(sbase + (MV_OFF + s * 64) * 4 + tid * 16, Mg + koffs + tid * 4);
        CP_COMMIT();
    }

    int stg = 0;
    for (int jb = 0; jb <= jbmax; jb++) {
        CP_WAIT1();
        __syncthreads();

        if (jb + 2 <= jbmax) {
            int ns = stg + 2; if (ns >= ASTG) ns -= ASTG;
            uint32_t ko = (KS_OFF + ns * 64 * KQ) * 4;
            uint32_t vo = (VT_OFF + ns * 64 * KQ) * 4;
            int koffs = (jb + 2) * 64;
            #pragma unroll
            for (int i = 0; i < 2; i++) {
                CP_ASYNC16(sbase + ko + (stgRow[i] * KQ + stgW4[i] * 4) * 4,
                           Kg + (size_t)(koffs + stgRow[i]) * HDIM + stgW4[i] * 8);
                CP_ASYNC16(sbase + vo + (stgRow[i] * KQ + stgW4[i] * 4) * 4,
                           Vg + (size_t)stgRow[i] * SS + koffs + stgW4[i] * 8);
            }
            if (tid < 16) CP_ASYNC16(sbase + (MV_OFF + ns * 64) * 4 + tid * 16,
                                     Mg + koffs + tid * 4);
        }
        CP_COMMIT();

        uint32_t ksb = sbase + (KS_OFF + stg * 64 * KQ) * 4;
        uint32_t vtb = sbase + (VT_OFF + stg * 64 * KQ) * 4;
        const float* mv = (const float*)(sm2 + MV_OFF + stg * 64);

        // S = Q K^T
        float sf[8][4];
        #pragma unroll
        for (int nt = 0; nt < 8; nt++)
            #pragma unroll
            for (int c = 0; c < 4; c++) sf[nt][c] = 0.0f;

        #pragma unroll
        for (int ks = 0; ks < 4; ks++) {
            uint32_t kb = ks * 32;
            uint32_t a0, a1, a2, a3;
            ldsm4(a0, a1, a2, a3, aq + kb);
            #pragma unroll
            for (int np = 0; np < 4; np++) {
                uint32_t b0, b1, b2, b3;
                ldsm4(b0, b1, b2, b3, ksb + bk[np] + kb);
                mma_f16(sf[2*np][0], sf[2*np][1], sf[2*np][2], sf[2*np][3],
                        a0, a1, a2, a3, b0, b1);
                mma_f16(sf[2*np+1][0], sf[2*np+1][1], sf[2*np+1][2], sf[2*np+1][3],
                        a0, a1, a2, a3, b2, b3);
            }
        }

        float rmax0 = NEG_BIG, rmax1 = NEG_BIG;
        #pragma unroll
        for (int nt = 0; nt < 8; nt++) {
            int cg = jb * 64 + nt * 8 + lc * 2;
            float pma = -10000.0f * (1.0f - mv[nt * 8 + lc * 2]);
            float pmb = -10000.0f * (1.0f - mv[nt * 8 + lc * 2 + 1]);
            float v0 = sf[nt][0] * 0.125f + pma; if (cg     > row_g0) v0 = NEG_BIG;
            float v1 = sf[nt][1] * 0.125f + pmb; if (cg + 1 > row_g0) v1 = NEG_BIG;
            float v2 = sf[nt][2] * 0.125f + pma; if (cg     > row_g1) v2 = NEG_BIG;
            float v3 = sf[nt][3] * 0.125f + pmb; if (cg + 1 > row_g1) v3 = NEG_BIG;
            sf[nt][0] = v0; sf[nt][1] = v1; sf[nt][2] = v2; sf[nt][3] = v3;
            rmax0 = fmaxf(rmax0, fmaxf(v0, v1));
            rmax1 = fmaxf(rmax1, fmaxf(v2, v3));
        }
        rmax0 = fmaxf(rmax0, __shfl_xor_sync(0xffffffffu, rmax0, 1));
        rmax0 = fmaxf(rmax0, __shfl_xor_sync(0xffffffffu, rmax0, 2));
        rmax1 = fmaxf(rmax1, __shfl_xor_sync(0xffffffffu, rmax1, 1));
        rmax1 = fmaxf(rmax1, __shfl_xor_sync(0xffffffffu, rmax1, 2));

        float mn0 = fmaxf(m0, rmax0), mn1 = fmaxf(m1, rmax1);
        float sc0 = __expf(m0 - mn0), sc1 = __expf(m1 - mn1);
        m0 = mn0; m1 = mn1;

        float ls0 = 0.0f, ls1 = 0.0f;
        #pragma unroll
        for (int nt = 0; nt < 8; nt++) {
            float p0 = __expf(sf[nt][0] - mn0);
            float p1 = __expf(sf[nt][1] - mn0);
            float p2 = __expf(sf[nt][2] - mn1);
            float p3 = __expf(sf[nt][3] - mn1);
            ls0 += p0 + p1; ls1 += p2 + p3;
            __half2 w0 = __floats2half2_rn(p0, p1);
            __half2 w1 = __floats2half2_rn(p2, p3);
            Ps[arow0 + nt * 4 + lc] = *(uint32_t*)&w0;
            Ps[arow1 + nt * 4 + lc] = *(uint32_t*)&w1;
            of[nt][0] *= sc0; of[nt][1] *= sc0;
            of[nt][2] *= sc1; of[nt][3] *= sc1;
        }
        ls0 += __shfl_xor_sync(0xffffffffu, ls0, 1);
        ls0 += __shfl_xor_sync(0xffffffffu, ls0, 2);
        ls1 += __shfl_xor_sync(0xffffffffu, ls1, 1);
        ls1 += __shfl_xor_sync(0xffffffffu, ls1, 2);
        l0 = l0 * sc0 + ls0;
        l1 = l1 * sc1 + ls1;

        __syncwarp();

        // O += P V
        #pragma unroll
        for (int ks = 0; ks < 4; ks++) {
            uint32_t kb = ks * 32;
            uint32_t a0, a1, a2, a3;
            ldsm4(a0, a1, a2, a3, ap + kb);
            #pragma unroll
            for (int np = 0; np < 4; np++) {
                uint32_t b0, b1, b2, b3;
                ldsm4(b0, b1, b2, b3, vtb + bk[np] + kb);
                mma_f16(of[2*np][0], of[2*np][1], of[2*np][2], of[2*np][3],
                        a0, a1, a2, a3, b0, b1);
                mma_f16(of[2*np+1][0], of[2*np+1][1], of[2*np+1][2], of[2*np+1][3],
                        a0, a1, a2, a3, b2, b3);
            }
        }

        if (++stg >= ASTG) stg = 0;
    }

    float inv0 = 1.0f / l0, inv1 = 1.0f / l1;
    size_t r0w = ((size_t)b * SS + qb * 128 + wm + lr) * DD + h * HDIM;
    size_t r1w = r0w + (size_t)8 * DD;
    #pragma unroll
    for (int nt = 0; nt < 8; nt++) {
        __half2 o0 = __floats2half2_rn(of[nt][0] * inv0, of[nt][1] * inv0);
        __half2 o1 = __floats2half2_rn(of[nt][2] * inv1, of[nt][3] * inv1);
        *(__half2*)(g_ao + r0w + nt * 8 + lc * 2) = o0;
        *(__half2*)(g_ao + r1w + nt * 8 + lc * 2) = o1;
    }
}

// ---------------------------------------------------------------------------
extern "C" void kernel_launch(void* const* d_in, const int* in_sizes, int n_in,
                              void* d_out, int out_size)
{
    const float* x     = (const float*)d_in[0];
    const float* amask = (const float*)d_in[1];
    const float* Wq    = (const float*)d_in[2];
    const float* bq    = (const float*)d_in[3];
    const float* Wk    = (const float*)d_in[4];
    const float* bk    = (const float*)d_in[5];
    const float* Wv    = (const float*)d_in[6];
    const float* bv    = (const float*)d_in[7];
    const float* Wo    = (const float*)d_in[8];
    const float* bo    = (const float*)d_in[9];
    const float* gam   = (const float*)d_in[10];
    const float* bet   = (const float*)d_in[11];
    float* out = (float*)d_out;

    cudaFuncSetAttribute(attn_h,
                         cudaFuncAttributeMaxDynamicSharedMemorySize,
                         ATTN_SMEM_BYTES);
    cudaFuncSetAttribute(gemm_h,
                         cudaFuncAttributeMaxDynamicSharedMemorySize,
                         GEMM_SMEM_BYTES);

    dim3 cvgrid(DD * DD / 4 / 256, 4);   // (1024, 4)
    cvtw_all<<<cvgrid, 256>>>(Wq, Wk, Wv, Wo);
    bias_kernel<<<12, 256>>>(bq, bk, bv);

    ln_kernel<<<MM/8, 256>>>(x, gam, bet);

    dim3 qkvgrid(3*DD/64, MM/128);    // (48, 64) = 3072 CTAs
    gemm_h<<<qkvgrid, 256, GEMM_SMEM_BYTES>>>(0, nullptr, nullptr, nullptr);

    dim3 agrid(SS/128, BB*HH);        // (16, 64)
    attn_h<<<agrid, 256, ATTN_SMEM_BYTES>>>(amask);

    dim3 ogrid(DD/64, MM/128);        // (16, 64) = 1024 CTAs
    gemm_h<<<ogrid, 256, GEMM_SMEM_BYTES>>>(1, bo, x, out);
}

// round 14
// speedup vs baseline: 1.0686x; 1.0686x over previous
#include <cuda_runtime.h>
#include <cuda_fp16.h>
#include <cstdint>
#include <math.h>

#define BB   4
#define SS   2048
#define DD   1024
#define HH   16
#define HDIM 64
#define MM   (BB*SS)          // 8192

#define NEG_BIG (-1e30f)

// Scratch (device globals)
__device__ __half g_xn[MM*DD];        // LN output, fp16
__device__ __half g_q [MM*DD];        // [B,H,S,Hd]
__device__ __half g_k [MM*DD];        // [B,H,S,Hd]
__device__ __half g_v [MM*DD];        // [B,H,Hd,S]  (head-transposed)
__device__ __half g_ao[MM*DD];        // [B,S,D]
__device__ __half g_wt[4*DD*DD];      // fp16 weights (q,k,v,o contiguous)
__device__ float  g_bias[3*DD];       // combined qkv bias

__device__ __forceinline__ uint32_t smem_u32(const void* p) {
    uint32_t a;
    asm("{ .reg .u64 t; cvta.to.shared.u64 t, %1; cvt.u32.u64 %0, t; }" : "=r"(a) : "l"(p));
    return a;
}
#define CP_ASYNC16(dst, src) \
    asm volatile("cp.async.cg.shared.global [%0], [%1], 16;" :: "r"(dst), "l"(src))
#define CP_COMMIT() asm volatile("cp.async.commit_group;" ::: "memory")
#define CP_WAIT1()  asm volatile("cp.async.wait_group 1;" ::: "memory")
#define CP_WAIT0()  asm volatile("cp.async.wait_group 0;" ::: "memory")

__device__ __forceinline__ void mma_f16(float& c0, float& c1, float& c2, float& c3,
                                        uint32_t a0, uint32_t a1, uint32_t a2, uint32_t a3,
                                        uint32_t b0, uint32_t b1) {
    asm volatile(
        "mma.sync.aligned.m16n8k16.row.col.f32.f16.f16.f32 "
        "{%0,%1,%2,%3}, {%4,%5,%6,%7}, {%8,%9}, {%0,%1,%2,%3};"
        : "+f"(c0), "+f"(c1), "+f"(c2), "+f"(c3)
        : "r"(a0), "r"(a1), "r"(a2), "r"(a3), "r"(b0), "r"(b1));
}
__device__ __forceinline__ void ldsm4(uint32_t& r0, uint32_t& r1, uint32_t& r2, uint32_t& r3,
                                      uint32_t a) {
    asm volatile("ldmatrix.sync.aligned.m8n8.x4.shared.b16 {%0,%1,%2,%3}, [%4];"
                 : "=r"(r0), "=r"(r1), "=r"(r2), "=r"(r3) : "r"(a));
}

// ---------------------------------------------------------------------------
// Prep kernels
// ---------------------------------------------------------------------------
__global__ __launch_bounds__(256) void cvtw_all(
    const float* __restrict__ w0, const float* __restrict__ w1,
    const float* __restrict__ w2, const float* __restrict__ w3)
{
    int widx = blockIdx.y;
    const float* w = (widx == 0) ? w0 : (widx == 1) ? w1 : (widx == 2) ? w2 : w3;
    int i = blockIdx.x * 256 + threadIdx.x;
    float4 v = ((const float4*)w)[i];
    __half2 h01 = __floats2half2_rn(v.x, v.y);
    __half2 h23 = __floats2half2_rn(v.z, v.w);
    uint2 u; u.x = *(uint32_t*)&h01; u.y = *(uint32_t*)&h23;
    ((uint2*)(g_wt + (size_t)widx * DD * DD))[i] = u;
}

__global__ __launch_bounds__(256) void bias_kernel(
    const float* __restrict__ bq, const float* __restrict__ bk, const float* __restrict__ bv)
{
    int i = blockIdx.x * 256 + threadIdx.x;   // 0..3071
    const float* src = (i < DD) ? bq : (i < 2*DD) ? bk : bv;
    g_bias[i] = src[i & (DD-1)];
}

// ---------------------------------------------------------------------------
// LayerNorm: one WARP per row, 8 rows/block.
// ---------------------------------------------------------------------------
__global__ __launch_bounds__(256) void ln_kernel(
    const float* __restrict__ x,
    const float* __restrict__ gamma,
    const float* __restrict__ beta)
{
    int row  = blockIdx.x * 8 + (threadIdx.x >> 5);
    int lane = threadIdx.x & 31;
    const float4* xr = (const float4*)(x + (size_t)row * DD);

    float4 v[8];
    float s = 0.0f;
    #pragma unroll
    for (int i = 0; i < 8; i++) {
        v[i] = xr[lane + 32*i];
        s += v[i].x + v[i].y + v[i].z + v[i].w;
    }
    #pragma unroll
    for (int o = 16; o > 0; o >>= 1) s += __shfl_xor_sync(0xffffffffu, s, o);
    float mean = s * (1.0f / DD);

    float s2 = 0.0f;
    #pragma unroll
    for (int i = 0; i < 8; i++) {
        v[i].x -= mean; v[i].y -= mean; v[i].z -= mean; v[i].w -= mean;
        s2 += v[i].x*v[i].x + v[i].y*v[i].y + v[i].z*v[i].z + v[i].w*v[i].w;
    }
    #pragma unroll
    for (int o = 16; o > 0; o >>= 1) s2 += __shfl_xor_sync(0xffffffffu, s2, o);
    float rstd = rsqrtf(s2 * (1.0f / DD) + 1e-5f);

    uint2* dst = (uint2*)(g_xn + (size_t)row * DD);
    #pragma unroll
    for (int i = 0; i < 8; i++) {
        float4 g  = ((const float4*)gamma)[lane + 32*i];
        float4 bb = ((const float4*)beta)[lane + 32*i];
        __half2 h01 = __floats2half2_rn(v[i].x * rstd * g.x + bb.x, v[i].y * rstd * g.y + bb.y);
        __half2 h23 = __floats2half2_rn(v[i].z * rstd * g.z + bb.z, v[i].w * rstd * g.w + bb.w);
        uint2 u; u.x = *(uint32_t*)&h01; u.y = *(uint32_t*)&h23;
        dst[lane + 32*i] = u;
    }
}

// ---------------------------------------------------------------------------
// fp16 tensor GEMM (R12 config): 128x128 tile, BK=64, 3-stage cp.async ring.
// 8 warps (4m x 2n), warp tile 32x64.
// mode 0: fused QKV; mode 1: output GEMM (+bias,+resid, fp32 out)
// ---------------------------------------------------------------------------
#define KP3 36
#define MW3 (128 * KP3)                     // words per matrix buffer (4608)
#define GSTG 3
#define GEMM_SMEM_BYTES (GSTG * 2 * MW3 * 4)   // 110592

__global__ __launch_bounds__(256, 2) void gemm_h(
    int mode,
    const float* __restrict__ bias_o,
    const float* __restrict__ resid,
    float* __restrict__ out)
{
    extern __shared__ uint32_t smem[];
    const __half* A = mode ? g_ao : g_xn;
    const __half* W = mode ? (g_wt + (size_t)3 * DD * DD) : g_wt;

    int tid = threadIdx.x;
    int wid = tid >> 5, lane = tid & 31;
    int m0 = blockIdx.y * 128;
    int n0 = blockIdx.x * 128;

    int wm = (wid & 3) * 32;
    int wn = (wid >> 2) * 64;
    int lr = lane >> 2;
    int lc = lane & 3;

    uint32_t sbase = smem_u32(smem);

    int srow[4], sc8[4];
    uint32_t sdstA[4], sdstB[4];
    const __half* agp[4];
    const __half* wgp[4];
    #pragma unroll
    for (int i = 0; i < 4; i++) {
        int f = tid + i * 256;
        srow[i] = f >> 3;
        sc8[i]  = f & 7;
        sdstA[i] = sbase + (srow[i] * KP3 + sc8[i] * 4) * 4;
        sdstB[i] = sdstA[i] + MW3 * 4;
        agp[i] = A + (size_t)(m0 + srow[i]) * DD + sc8[i] * 8;
        wgp[i] = W + (size_t)(n0 + srow[i]) * DD + sc8[i] * 8;
    }

    uint32_t aoff[2], boff[4];
    #pragma unroll
    for (int tm = 0; tm < 2; tm++)
        aoff[tm] = ((wm + tm * 16 + (lane & 15)) * KP3 + ((lane >> 4) << 2)) * 4;
    #pragma unroll
    for (int np = 0; np < 4; np++)
        boff[np] = MW3 * 4 +
            ((wn + np * 16 + (lane & 7) + ((lane >> 4) << 3)) * KP3 + (((lane >> 3) & 1) << 2)) * 4;

    float acc[2][8][4];
    #pragma unroll
    for (int tm = 0; tm < 2; tm++)
        #pragma unroll
        for (int tn = 0; tn < 8; tn++)
            #pragma unroll
            for (int c = 0; c < 4; c++) acc[tm][tn][c] = 0.0f;

    #pragma unroll
    for (int s = 0; s < 2; s++) {
        uint32_t so = s * 2 * MW3 * 4;
        #pragma unroll
        for (int i = 0; i < 4; i++) {
            CP_ASYNC16(sdstA[i] + so, agp[i] + s * 64);
            CP_ASYNC16(sdstB[i] + so, wgp[i] + s * 64);
        }
        CP_COMMIT();
    }

    int stg = 0;
    for (int kt = 0; kt < 16; kt++) {
        CP_WAIT1();
        __syncthreads();

        if (kt + 2 < 16) {
            int ns = stg + 2; if (ns >= GSTG) ns -= GSTG;
            uint32_t so = ns * 2 * MW3 * 4;
            int k0n = (kt + 2) * 64;
            #pragma unroll
            for (int i = 0; i < 4; i++) {
                CP_ASYNC16(sdstA[i] + so, agp[i] + k0n);
                CP_ASYNC16(sdstB[i] + so, wgp[i] + k0n);
            }
        }
        CP_COMMIT();

        uint32_t bb = sbase + stg * 2 * MW3 * 4;
        #pragma unroll
        for (int ks = 0; ks < 4; ks++) {
            uint32_t kb = ks * 32;
            uint32_t a0,a1,a2,a3, c0,c1,c2,c3;
            ldsm4(a0, a1, a2, a3, bb + aoff[0] + kb);
            ldsm4(c0, c1, c2, c3, bb + aoff[1] + kb);
            #pragma unroll
            for (int np = 0; np < 4; np++) {
                uint32_t b0, b1, b2, b3;
                ldsm4(b0, b1, b2, b3, bb + boff[np] + kb);
                mma_f16(acc[0][2*np][0], acc[0][2*np][1], acc[0][2*np][2], acc[0][2*np][3],
                        a0, a1, a2, a3, b0, b1);
                mma_f16(acc[0][2*np+1][0], acc[0][2*np+1][1], acc[0][2*np+1][2], acc[0][2*np+1][3],
                        a0, a1, a2, a3, b2, b3);
                mma_f16(acc[1][2*np][0], acc[1][2*np][1], acc[1][2*np][2], acc[1][2*np][3],
                        c0, c1, c2, c3, b0, b1);
                mma_f16(acc[1][2*np+1][0], acc[1][2*np+1][1], acc[1][2*np+1][2], acc[1][2*np+1][3],
                        c0, c1, c2, c3, b2, b3);
            }
        }
        if (++stg >= GSTG) stg = 0;
    }

    CP_WAIT0();
    __syncthreads();

    int bI = m0 >> 11, s0 = m0 & (SS - 1);

    if (mode == 0) {
        int sel = n0 >> 10;
        if (sel < 2) {
            __half* dst0 = (sel == 0) ? g_q : g_k;
            #pragma unroll
            for (int tm = 0; tm < 2; tm++)
                #pragma unroll
                for (int half = 0; half < 2; half++) {
                    int sI = s0 + wm + tm * 16 + lr + half * 8;
                    #pragma unroll
                    for (int tn = 0; tn < 8; tn++) {
                        int n = n0 + wn + tn * 8 + lc * 2;
                        float r0 = acc[tm][tn][half*2+0] + g_bias[n];
                        float r1 = acc[tm][tn][half*2+1] + g_bias[n+1];
                        int nn = n & (DD - 1);
                        int h = nn >> 6, hd = nn & 63;
                        __half2 hv = __floats2half2_rn(r0, r1);
                        size_t idx = ((size_t)(bI * HH + h) * SS + sI) * HDIM + hd;
                        *(__half2*)(dst0 + idx) = hv;
                    }
                }
        } else {
            // V: transpose 128x128 tile via smem, then coalesced stores along S
            const int TP = 136;
            __half* sT = (__half*)smem;
            #pragma unroll
            for (int tm = 0; tm < 2; tm++)
                #pragma unroll
                for (int half = 0; half < 2; half++) {
                    int ml = wm + tm * 16 + lr + half * 8;
                    #pragma unroll
                    for (int tn = 0; tn < 8; tn++) {
                        int nl = wn + tn * 8 + lc * 2;
                        int n = n0 + nl;
                        sT[nl * TP + ml]     = __float2half_rn(acc[tm][tn][half*2+0] + g_bias[n]);
                        sT[(nl+1) * TP + ml] = __float2half_rn(acc[tm][tn][half*2+1] + g_bias[n+1]);
                    }
                }
            __syncthreads();
            #pragma unroll
            for (int j = 0; j < 8; j++) {
                int f = tid + j * 256;     // 0..2047
                int r = f >> 4, c = f & 15;
                uint4 val = *(const uint4*)(sT + r * TP + c * 8);
                int nglob = n0 - 2 * DD + r;
                int h = nglob >> 6, hd = nglob & 63;
                *(uint4*)(g_v + ((size_t)(bI * HH + h) * HDIM + hd) * SS + s0 + c * 8) = val;
            }
        }
    } else {
        #pragma unroll
        for (int tm = 0; tm < 2; tm++)
            #pragma unroll
            for (int half = 0; half < 2; half++) {
                int m = m0 + wm + tm * 16 + lr + half * 8;
                #pragma unroll
                for (int tn = 0; tn < 8; tn++) {
                    int n = n0 + wn + tn * 8 + lc * 2;
                    float2 bz = *(const float2*)(bias_o + n);
                    size_t idx = (size_t)m * DD + n;
                    float2 rv = *(const float2*)(resid + idx);
                    float2 r;
                    r.x = acc[tm][tn][half*2+0] + bz.x + rv.x;
                    r.y = acc[tm][tn][half*2+1] + bz.y + rv.y;
                    *(float2*)(out + idx) = r;
                }
            }
    }
}

// ---------------------------------------------------------------------------
// fp16 tensor-core causal flash attention, 3-stage K/V ring, one sync/iter.
// P kept entirely in registers (C-fragment == A-fragment layout).
// 128 queries x 64 keys per iter, Hd=64, 8 warps (warp = 16 rows).
// grid: (S/128 = 16, B*H = 64)
// ---------------------------------------------------------------------------
#define KQ 36
#define ASTG 3
#define QS_OFF 0
#define KS_OFF (128*KQ)                     // + stg*64*KQ
#define VT_OFF (KS_OFF + ASTG*64*KQ)        // + stg*64*KQ
#define MV_OFF (VT_OFF + ASTG*64*KQ)        // + stg*64
#define ATTN_WORDS (MV_OFF + ASTG*64)
#define ATTN_SMEM_BYTES (ATTN_WORDS * 4)    // 74496

__global__ __launch_bounds__(256, 2) void attn_h(const float* __restrict__ mask)
{
    extern __shared__ uint32_t sm2[];
    uint32_t sbase = smem_u32(sm2);

    int qb = (int)gridDim.x - 1 - (int)blockIdx.x;   // heavy blocks first
    int bh = blockIdx.y;
    int b = bh >> 4, h = bh & 15;

    const __half* Qg = g_q + ((size_t)bh * SS + qb * 128) * HDIM;
    const __half* Kg = g_k + (size_t)bh * SS * HDIM;
    const __half* Vg = g_v + (size_t)bh * HDIM * SS;   // [d][s]
    const float*  Mg = mask + b * SS;

    int tid = threadIdx.x;
    int wid = tid >> 5, lane = tid & 31;
    int lr = lane >> 2, lc = lane & 3;
    int wm = wid * 16;

    // stage Q
    #pragma unroll
    for (int i = 0; i < 4; i++) {
        int c = tid + i * 256;
        int row = c >> 3, w4 = c & 7;
        uint4 t = *(const uint4*)(Qg + row * HDIM + w4 * 8);
        *(uint4*)((char*)sm2 + (QS_OFF + row * KQ + w4 * 4) * 4) = t;
    }

    uint32_t aq = sbase + (QS_OFF + (wm + (lane & 15)) * KQ + ((lane >> 4) << 2)) * 4;
    uint32_t bk[4];
    #pragma unroll
    for (int np = 0; np < 4; np++)
        bk[np] = ((np * 16 + (lane & 7) + ((lane >> 4) << 3)) * KQ + (((lane >> 3) & 1) << 2)) * 4;

    int stgRow[2], stgW4[2];
    #pragma unroll
    for (int i = 0; i < 2; i++) {
        int c = tid + i * 256;
        stgRow[i] = c >> 3; stgW4[i] = c & 7;
    }

    float of[8][4];
    #pragma unroll
    for (int nt = 0; nt < 8; nt++)
        #pragma unroll
        for (int c = 0; c < 4; c++) of[nt][c] = 0.0f;
    float m0 = NEG_BIG, m1 = NEG_BIG, l0 = 0.0f, l1 = 0.0f;

    int row_g0 = qb * 128 + wm + lr;
    int row_g1 = row_g0 + 8;

    int jbmax = 2 * qb + 1;

    // prologue: stages for jb=0,1
    #pragma unroll
    for (int s = 0; s < 2; s++) {
        uint32_t ko = (KS_OFF + s * 64 * KQ) * 4;
        uint32_t vo = (VT_OFF + s * 64 * KQ) * 4;
        int koffs = s * 64;
        #pragma unroll
        for (int i = 0; i < 2; i++) {
            CP_ASYNC16(sbase + ko + (stgRow[i] * KQ + stgW4[i] * 4) * 4,
                       Kg + (size_t)(koffs + stgRow[i]) * HDIM + stgW4[i] * 8);
            CP_ASYNC16(sbase + vo + (stgRow[i] * KQ + stgW4[i] * 4) * 4,
                       Vg + (size_t)stgRow[i] * SS + koffs + stgW4[i] * 8);
        }
        if (tid < 16) CP_ASYNC16(sbase + (MV_OFF + s * 64) * 4 + tid * 16, Mg + koffs + tid * 4);
        CP_COMMIT();
    }

    int stg = 0;
    for (int jb = 0; jb <= jbmax; jb++) {
        CP_WAIT1();
        __syncthreads();

        if (jb + 2 <= jbmax) {
            int ns = stg + 2; if (ns >= ASTG) ns -= ASTG;
            uint32_t ko = (KS_OFF + ns * 64 * KQ) * 4;
            uint32_t vo = (VT_OFF + ns * 64 * KQ) * 4;
            int koffs = (jb + 2) * 64;
            #pragma unroll
            for (int i = 0; i < 2; i++) {
                CP_ASYNC16(sbase + ko + (stgRow[i] * KQ + stgW4[i] * 4) * 4,
                           Kg + (size_t)(koffs + stgRow[i]) * HDIM + stgW4[i] * 8);
                CP_ASYNC16(sbase + vo + (stgRow[i] * KQ + stgW4[i] * 4) * 4,
                           Vg + (size_t)stgRow[i] * SS + koffs + stgW4[i] * 8);
            }
            if (tid < 16) CP_ASYNC16(sbase + (MV_OFF + ns * 64) * 4 + tid * 16,
                                     Mg + koffs + tid * 4);
        }
        CP_COMMIT();

        uint32_t ksb = sbase + (KS_OFF + stg * 64 * KQ) * 4;
        uint32_t vtb = sbase + (VT_OFF + stg * 64 * KQ) * 4;
        const float* mv = (const float*)(sm2 + MV_OFF + stg * 64);

        // S = Q K^T
        float sf[8][4];
        #pragma unroll
        for (int nt = 0; nt < 8; nt++)
            #pragma unroll
            for (int c = 0; c < 4; c++) sf[nt][c] = 0.0f;

        #pragma unroll
        for (int ks = 0; ks < 4; ks++) {
            uint32_t kb = ks * 32;
            uint32_t a0, a1, a2, a3;
            ldsm4(a0, a1, a2, a3, aq + kb);
            #pragma unroll
            for (int np = 0; np < 4; np++) {
                uint32_t b0, b1, b2, b3;
                ldsm4(b0, b1, b2, b3, ksb + bk[np] + kb);
                mma_f16(sf[2*np][0], sf[2*np][1], sf[2*np][2], sf[2*np][3],
                        a0, a1, a2, a3, b0, b1);
                mma_f16(sf[2*np+1][0], sf[2*np+1][1], sf[2*np+1][2], sf[2*np+1][3],
                        a0, a1, a2, a3, b2, b3);
            }
        }

        float rmax0 = NEG_BIG, rmax1 = NEG_BIG;
        #pragma unroll
        for (int nt = 0; nt < 8; nt++) {
            int cg = jb * 64 + nt * 8 + lc * 2;
            float pma = -10000.0f * (1.0f - mv[nt * 8 + lc * 2]);
            float pmb = -10000.0f * (1.0f - mv[nt * 8 + lc * 2 + 1]);
            float v0 = sf[nt][0] * 0.125f + pma; if (cg     > row_g0) v0 = NEG_BIG;
            float v1 = sf[nt][1] * 0.125f + pmb; if (cg + 1 > row_g0) v1 = NEG_BIG;
            float v2 = sf[nt][2] * 0.125f + pma; if (cg     > row_g1) v2 = NEG_BIG;
            float v3 = sf[nt][3] * 0.125f + pmb; if (cg + 1 > row_g1) v3 = NEG_BIG;
            sf[nt][0] = v0; sf[nt][1] = v1; sf[nt][2] = v2; sf[nt][3] = v3;
            rmax0 = fmaxf(rmax0, fmaxf(v0, v1));
            rmax1 = fmaxf(rmax1, fmaxf(v2, v3));
        }
        rmax0 = fmaxf(rmax0, __shfl_xor_sync(0xffffffffu, rmax0, 1));
        rmax0 = fmaxf(rmax0, __shfl_xor_sync(0xffffffffu, rmax0, 2));
        rmax1 = fmaxf(rmax1, __shfl_xor_sync(0xffffffffu, rmax1, 1));
        rmax1 = fmaxf(rmax1, __shfl_xor_sync(0xffffffffu, rmax1, 2));

        float mn0 = fmaxf(m0, rmax0), mn1 = fmaxf(m1, rmax1);
        float sc0 = __expf(m0 - mn0), sc1 = __expf(m1 - mn1);
        m0 = mn0; m1 = mn1;

        // exp + pack P straight into A-fragments (C-frag == A-frag layout)
        uint32_t ph2[8][2];
        float ls0 = 0.0f, ls1 = 0.0f;
        #pragma unroll
        for (int nt = 0; nt < 8; nt++) {
            float p0 = __expf(sf[nt][0] - mn0);
            float p1 = __expf(sf[nt][1] - mn0);
            float p2 = __expf(sf[nt][2] - mn1);
            float p3 = __expf(sf[nt][3] - mn1);
            ls0 += p0 + p1; ls1 += p2 + p3;
            __half2 w0 = __floats2half2_rn(p0, p1);
            __half2 w1 = __floats2half2_rn(p2, p3);
            ph2[nt][0] = *(uint32_t*)&w0;   // rows lr,  k = tile cols
            ph2[nt][1] = *(uint32_t*)&w1;   // rows lr+8
            of[nt][0] *= sc0; of[nt][1] *= sc0;
            of[nt][2] *= sc1; of[nt][3] *= sc1;
        }
        ls0 += __shfl_xor_sync(0xffffffffu, ls0, 1);
        ls0 += __shfl_xor_sync(0xffffffffu, ls0, 2);
        ls1 += __shfl_xor_sync(0xffffffffu, ls1, 1);
        ls1 += __shfl_xor_sync(0xffffffffu, ls1, 2);
        l0 = l0 * sc0 + ls0;
        l1 = l1 * sc1 + ls1;

        // O += P V   (A = ph2 in registers, B = Vt fragments)
        #pragma unroll
        for (int ks = 0; ks < 4; ks++) {
            uint32_t kb = ks * 32;
            uint32_t a0 = ph2[2*ks][0];
            uint32_t a1 = ph2[2*ks][1];
            uint32_t a2 = ph2[2*ks+1][0];
            uint32_t a3 = ph2[2*ks+1][1];
            #pragma unroll
            for (int np = 0; np < 4; np++) {
                uint32_t b0, b1, b2, b3;
                ldsm4(b0, b1, b2, b3, vtb + bk[np] + kb);
                mma_f16(of[2*np][0], of[2*np][1], of[2*np][2], of[2*np][3],
                        a0, a1, a2, a3, b0, b1);
                mma_f16(of[2*np+1][0], of[2*np+1][1], of[2*np+1][2], of[2*np+1][3],
                        a0, a1, a2, a3, b2, b3);
            }
        }

        if (++stg >= ASTG) stg = 0;
    }

    float inv0 = 1.0f / l0, inv1 = 1.0f / l1;
    size_t r0w = ((size_t)b * SS + qb * 128 + wm + lr) * DD + h * HDIM;
    size_t r1w = r0w + (size_t)8 * DD;
    #pragma unroll
    for (int nt = 0; nt < 8; nt++) {
        __half2 o0 = __floats2half2_rn(of[nt][0] * inv0, of[nt][1] * inv0);
        __half2 o1 = __floats2half2_rn(of[nt][2] * inv1, of[nt][3] * inv1);
        *(__half2*)(g_ao + r0w + nt * 8 + lc * 2) = o0;
        *(__half2*)(g_ao + r1w + nt * 8 + lc * 2) = o1;
    }
}

// ---------------------------------------------------------------------------
extern "C" void kernel_launch(void* const* d_in, const int* in_sizes, int n_in,
                              void* d_out, int out_size)
{
    const float* x     = (const float*)d_in[0];
    const float* amask = (const float*)d_in[1];
    const float* Wq    = (const float*)d_in[2];
    const float* bq    = (const float*)d_in[3];
    const float* Wk    = (const float*)d_in[4];
    const float* bk    = (const float*)d_in[5];
    const float* Wv    = (const float*)d_in[6];
    const float* bv    = (const float*)d_in[7];
    const float* Wo    = (const float*)d_in[8];
    const float* bo    = (const float*)d_in[9];
    const float* gam   = (const float*)d_in[10];
    const float* bet   = (const float*)d_in[11];
    float* out = (float*)d_out;

    cudaFuncSetAttribute(attn_h,
                         cudaFuncAttributeMaxDynamicSharedMemorySize,
                         ATTN_SMEM_BYTES);
    cudaFuncSetAttribute(gemm_h,
                         cudaFuncAttributeMaxDynamicSharedMemorySize,
                         GEMM_SMEM_BYTES);

    dim3 cvgrid(DD * DD / 4 / 256, 4);   // (1024, 4)
    cvtw_all<<<cvgrid, 256>>>(Wq, Wk, Wv, Wo);
    bias_kernel<<<12, 256>>>(bq, bk, bv);

    ln_kernel<<<MM/8, 256>>>(x, gam, bet);

    dim3 qkvgrid(3*DD/128, MM/128);   // (24, 64)
    gemm_h<<<qkvgrid, 256, GEMM_SMEM_BYTES>>>(0, nullptr, nullptr, nullptr);

    dim3 agrid(SS/128, BB*HH);        // (16, 64)
    attn_h<<<agrid, 256, ATTN_SMEM_BYTES>>>(amask);

    dim3 ogrid(DD/128, MM/128);       // (8, 64)
    gemm_h<<<ogrid, 256, GEMM_SMEM_BYTES>>>(1, bo, x, out);
}

// round 15
// speedup vs baseline: 1.1088x; 1.0376x over previous
#include <cuda_runtime.h>
#include <cuda_fp16.h>
#include <cstdint>
#include <math.h>

#define BB   4
#define SS   2048
#define DD   1024
#define HH   16
#define HDIM 64
#define MM   (BB*SS)          // 8192

#define NEG_BIG (-1e30f)

// Scratch (device globals)
__device__ __half g_xn[MM*DD];        // LN output, fp16
__device__ __half g_q [MM*DD];        // [B,H,S,Hd]
__device__ __half g_k [MM*DD];        // [B,H,S,Hd]
__device__ __half g_v [MM*DD];        // [B,H,Hd,S]  (head-transposed)
__device__ __half g_ao[MM*DD];        // [B,S,D]
__device__ __half g_wt[4*DD*DD];      // fp16 weights (q,k,v,o contiguous)
__device__ float  g_bias[3*DD];       // combined qkv bias

__device__ __forceinline__ uint32_t smem_u32(const void* p) {
    uint32_t a;
    asm("{ .reg .u64 t; cvta.to.shared.u64 t, %1; cvt.u32.u64 %0, t; }" : "=r"(a) : "l"(p));
    return a;
}
#define CP_ASYNC16(dst, src) \
    asm volatile("cp.async.cg.shared.global [%0], [%1], 16;" :: "r"(dst), "l"(src))
#define CP_COMMIT() asm volatile("cp.async.commit_group;" ::: "memory")
#define CP_WAIT1()  asm volatile("cp.async.wait_group 1;" ::: "memory")
#define CP_WAIT0()  asm volatile("cp.async.wait_group 0;" ::: "memory")

__device__ __forceinline__ void mma_f16(float& c0, float& c1, float& c2, float& c3,
                                        uint32_t a0, uint32_t a1, uint32_t a2, uint32_t a3,
                                        uint32_t b0, uint32_t b1) {
    asm volatile(
        "mma.sync.aligned.m16n8k16.row.col.f32.f16.f16.f32 "
        "{%0,%1,%2,%3}, {%4,%5,%6,%7}, {%8,%9}, {%0,%1,%2,%3};"
        : "+f"(c0), "+f"(c1), "+f"(c2), "+f"(c3)
        : "r"(a0), "r"(a1), "r"(a2), "r"(a3), "r"(b0), "r"(b1));
}
__device__ __forceinline__ void ldsm4(uint32_t& r0, uint32_t& r1, uint32_t& r2, uint32_t& r3,
                                      uint32_t a) {
    asm volatile("ldmatrix.sync.aligned.m8n8.x4.shared.b16 {%0,%1,%2,%3}, [%4];"
                 : "=r"(r0), "=r"(r1), "=r"(r2), "=r"(r3) : "r"(a));
}
__device__ __forceinline__ uint32_t ex2_h2(float x0, float x1) {
    __half2 hx = __floats2half2_rn(x0, x1);
    uint32_t r;
    asm("ex2.approx.f16x2 %0, %1;" : "=r"(r) : "r"(*(uint32_t*)&hx));
    return r;
}

// ---------------------------------------------------------------------------
// Prep kernels
// ---------------------------------------------------------------------------
__global__ __launch_bounds__(256) void cvtw_all(
    const float* __restrict__ w0, const float* __restrict__ w1,
    const float* __restrict__ w2, const float* __restrict__ w3)
{
    int widx = blockIdx.y;
    const float* w = (widx == 0) ? w0 : (widx == 1) ? w1 : (widx == 2) ? w2 : w3;
    int i = blockIdx.x * 256 + threadIdx.x;
    float4 v = ((const float4*)w)[i];
    __half2 h01 = __floats2half2_rn(v.x, v.y);
    __half2 h23 = __floats2half2_rn(v.z, v.w);
    uint2 u; u.x = *(uint32_t*)&h01; u.y = *(uint32_t*)&h23;
    ((uint2*)(g_wt + (size_t)widx * DD * DD))[i] = u;
}

__global__ __launch_bounds__(256) void bias_kernel(
    const float* __restrict__ bq, const float* __restrict__ bk, const float* __restrict__ bv)
{
    int i = blockIdx.x * 256 + threadIdx.x;   // 0..3071
    const float* src = (i < DD) ? bq : (i < 2*DD) ? bk : bv;
    g_bias[i] = src[i & (DD-1)];
}

// ---------------------------------------------------------------------------
// LayerNorm: one WARP per row, 8 rows/block.
// ---------------------------------------------------------------------------
__global__ __launch_bounds__(256) void ln_kernel(
    const float* __restrict__ x,
    const float* __restrict__ gamma,
    const float* __restrict__ beta)
{
    int row  = blockIdx.x * 8 + (threadIdx.x >> 5);
    int lane = threadIdx.x & 31;
    const float4* xr = (const float4*)(x + (size_t)row * DD);

    float4 v[8];
    float s = 0.0f;
    #pragma unroll
    for (int i = 0; i < 8; i++) {
        v[i] = xr[lane + 32*i];
        s += v[i].x + v[i].y + v[i].z + v[i].w;
    }
    #pragma unroll
    for (int o = 16; o > 0; o >>= 1) s += __shfl_xor_sync(0xffffffffu, s, o);
    float mean = s * (1.0f / DD);

    float s2 = 0.0f;
    #pragma unroll
    for (int i = 0; i < 8; i++) {
        v[i].x -= mean; v[i].y -= mean; v[i].z -= mean; v[i].w -= mean;
        s2 += v[i].x*v[i].x + v[i].y*v[i].y + v[i].z*v[i].z + v[i].w*v[i].w;
    }
    #pragma unroll
    for (int o = 16; o > 0; o >>= 1) s2 += __shfl_xor_sync(0xffffffffu, s2, o);
    float rstd = rsqrtf(s2 * (1.0f / DD) + 1e-5f);

    uint2* dst = (uint2*)(g_xn + (size_t)row * DD);
    #pragma unroll
    for (int i = 0; i < 8; i++) {
        float4 g  = ((const float4*)gamma)[lane + 32*i];
        float4 bb = ((const float4*)beta)[lane + 32*i];
        __half2 h01 = __floats2half2_rn(v[i].x * rstd * g.x + bb.x, v[i].y * rstd * g.y + bb.y);
        __half2 h23 = __floats2half2_rn(v[i].z * rstd * g.z + bb.z, v[i].w * rstd * g.w + bb.w);
        uint2 u; u.x = *(uint32_t*)&h01; u.y = *(uint32_t*)&h23;
        dst[lane + 32*i] = u;
    }
}

// ---------------------------------------------------------------------------
// fp16 tensor GEMM: 128x128 tile, BK=64, 3-stage cp.async ring.
// 8 warps (4m x 2n), warp tile 32x64.
// mode 0: fused QKV; mode 1: output GEMM (+bias,+resid, fp32 out)
// ---------------------------------------------------------------------------
#define KP3 36
#define MW3 (128 * KP3)                     // words per matrix buffer (4608)
#define GSTG 3
#define GEMM_SMEM_BYTES (GSTG * 2 * MW3 * 4)   // 110592

__global__ __launch_bounds__(256, 2) void gemm_h(
    int mode,
    const float* __restrict__ bias_o,
    const float* __restrict__ resid,
    float* __restrict__ out)
{
    extern __shared__ uint32_t smem[];
    const __half* A = mode ? g_ao : g_xn;
    const __half* W = mode ? (g_wt + (size_t)3 * DD * DD) : g_wt;

    int tid = threadIdx.x;
    int wid = tid >> 5, lane = tid & 31;
    int m0 = blockIdx.y * 128;
    int n0 = blockIdx.x * 128;

    int wm = (wid & 3) * 32;
    int wn = (wid >> 2) * 64;
    int lr = lane >> 2;
    int lc = lane & 3;

    uint32_t sbase = smem_u32(smem);

    int srow[4], sc8[4];
    uint32_t sdstA[4], sdstB[4];
    const __half* agp[4];
    const __half* wgp[4];
    #pragma unroll
    for (int i = 0; i < 4; i++) {
        int f = tid + i * 256;
        srow[i] = f >> 3;
        sc8[i]  = f & 7;
        sdstA[i] = sbase + (srow[i] * KP3 + sc8[i] * 4) * 4;
        sdstB[i] = sdstA[i] + MW3 * 4;
        agp[i] = A + (size_t)(m0 + srow[i]) * DD + sc8[i] * 8;
        wgp[i] = W + (size_t)(n0 + srow[i]) * DD + sc8[i] * 8;
    }

    uint32_t aoff[2], boff[4];
    #pragma unroll
    for (int tm = 0; tm < 2; tm++)
        aoff[tm] = ((wm + tm * 16 + (lane & 15)) * KP3 + ((lane >> 4) << 2)) * 4;
    #pragma unroll
    for (int np = 0; np < 4; np++)
        boff[np] = MW3 * 4 +
            ((wn + np * 16 + (lane & 7) + ((lane >> 4) << 3)) * KP3 + (((lane >> 3) & 1) << 2)) * 4;

    float acc[2][8][4];
    #pragma unroll
    for (int tm = 0; tm < 2; tm++)
        #pragma unroll
        for (int tn = 0; tn < 8; tn++)
            #pragma unroll
            for (int c = 0; c < 4; c++) acc[tm][tn][c] = 0.0f;

    #pragma unroll
    for (int s = 0; s < 2; s++) {
        uint32_t so = s * 2 * MW3 * 4;
        #pragma unroll
        for (int i = 0; i < 4; i++) {
            CP_ASYNC16(sdstA[i] + so, agp[i] + s * 64);
            CP_ASYNC16(sdstB[i] + so, wgp[i] + s * 64);
        }
        CP_COMMIT();
    }

    int stg = 0;
    for (int kt = 0; kt < 16; kt++) {
        CP_WAIT1();
        __syncthreads();

        if (kt + 2 < 16) {
            int ns = stg + 2; if (ns >= GSTG) ns -= GSTG;
            uint32_t so = ns * 2 * MW3 * 4;
            int k0n = (kt + 2) * 64;
            #pragma unroll
            for (int i = 0; i < 4; i++) {
                CP_ASYNC16(sdstA[i] + so, agp[i] + k0n);
                CP_ASYNC16(sdstB[i] + so, wgp[i] + k0n);
            }
        }
        CP_COMMIT();

        uint32_t bb = sbase + stg * 2 * MW3 * 4;
        #pragma unroll
        for (int ks = 0; ks < 4; ks++) {
            uint32_t kb = ks * 32;
            uint32_t a0,a1,a2,a3, c0,c1,c2,c3;
            ldsm4(a0, a1, a2, a3, bb + aoff[0] + kb);
            ldsm4(c0, c1, c2, c3, bb + aoff[1] + kb);
            #pragma unroll
            for (int np = 0; np < 4; np++) {
                uint32_t b0, b1, b2, b3;
                ldsm4(b0, b1, b2, b3, bb + boff[np] + kb);
                mma_f16(acc[0][2*np][0], acc[0][2*np][1], acc[0][2*np][2], acc[0][2*np][3],
                        a0, a1, a2, a3, b0, b1);
                mma_f16(acc[0][2*np+1][0], acc[0][2*np+1][1], acc[0][2*np+1][2], acc[0][2*np+1][3],
                        a0, a1, a2, a3, b2, b3);
                mma_f16(acc[1][2*np][0], acc[1][2*np][1], acc[1][2*np][2], acc[1][2*np][3],
                        c0, c1, c2, c3, b0, b1);
                mma_f16(acc[1][2*np+1][0], acc[1][2*np+1][1], acc[1][2*np+1][2], acc[1][2*np+1][3],
                        c0, c1, c2, c3, b2, b3);
            }
        }
        if (++stg >= GSTG) stg = 0;
    }

    CP_WAIT0();
    __syncthreads();

    int bI = m0 >> 11, s0 = m0 & (SS - 1);

    if (mode == 0) {
        int sel = n0 >> 10;
        if (sel < 2) {
            __half* dst0 = (sel == 0) ? g_q : g_k;
            #pragma unroll
            for (int tm = 0; tm < 2; tm++)
                #pragma unroll
                for (int half = 0; half < 2; half++) {
                    int sI = s0 + wm + tm * 16 + lr + half * 8;
                    #pragma unroll
                    for (int tn = 0; tn < 8; tn++) {
                        int n = n0 + wn + tn * 8 + lc * 2;
                        float r0 = acc[tm][tn][half*2+0] + g_bias[n];
                        float r1 = acc[tm][tn][half*2+1] + g_bias[n+1];
                        int nn = n & (DD - 1);
                        int h = nn >> 6, hd = nn & 63;
                        __half2 hv = __floats2half2_rn(r0, r1);
                        size_t idx = ((size_t)(bI * HH + h) * SS + sI) * HDIM + hd;
                        *(__half2*)(dst0 + idx) = hv;
                    }
                }
        } else {
            // V: transpose 128x128 tile via smem, then coalesced stores along S
            const int TP = 136;
            __half* sT = (__half*)smem;
            #pragma unroll
            for (int tm = 0; tm < 2; tm++)
                #pragma unroll
                for (int half = 0; half < 2; half++) {
                    int ml = wm + tm * 16 + lr + half * 8;
                    #pragma unroll
                    for (int tn = 0; tn < 8; tn++) {
                        int nl = wn + tn * 8 + lc * 2;
                        int n = n0 + nl;
                        sT[nl * TP + ml]     = __float2half_rn(acc[tm][tn][half*2+0] + g_bias[n]);
                        sT[(nl+1) * TP + ml] = __float2half_rn(acc[tm][tn][half*2+1] + g_bias[n+1]);
                    }
                }
            __syncthreads();
            #pragma unroll
            for (int j = 0; j < 8; j++) {
                int f = tid + j * 256;     // 0..2047
                int r = f >> 4, c = f & 15;
                uint4 val = *(const uint4*)(sT + r * TP + c * 8);
                int nglob = n0 - 2 * DD + r;
                int h = nglob >> 6, hd = nglob & 63;
                *(uint4*)(g_v + ((size_t)(bI * HH + h) * HDIM + hd) * SS + s0 + c * 8) = val;
            }
        }
    } else {
        #pragma unroll
        for (int tm = 0; tm < 2; tm++)
            #pragma unroll
            for (int half = 0; half < 2; half++) {
                int m = m0 + wm + tm * 16 + lr + half * 8;
                #pragma unroll
                for (int tn = 0; tn < 8; tn++) {
                    int n = n0 + wn + tn * 8 + lc * 2;
                    float2 bz = *(const float2*)(bias_o + n);
                    size_t idx = (size_t)m * DD + n;
                    float2 rv = *(const float2*)(resid + idx);
                    float2 r;
                    r.x = acc[tm][tn][half*2+0] + bz.x + rv.x;
                    r.y = acc[tm][tn][half*2+1] + bz.y + rv.y;
                    *(float2*)(out + idx) = r;
                }
            }
    }
}

// ---------------------------------------------------------------------------
// fp16 tensor-core causal flash attention, 3-stage K/V ring, one sync/iter.
// P in registers; softmax in base-2 domain with ex2.approx.f16x2.
// 128 queries x 64 keys per iter, Hd=64, 8 warps (warp = 16 rows).
// grid: (S/128 = 16, B*H = 64)
// ---------------------------------------------------------------------------
#define KQ 36
#define ASTG 3
#define QS_OFF 0
#define KS_OFF (128*KQ)                     // + stg*64*KQ
#define VT_OFF (KS_OFF + ASTG*64*KQ)        // + stg*64*KQ
#define MV_OFF (VT_OFF + ASTG*64*KQ)        // + stg*64
#define ATTN_WORDS (MV_OFF + ASTG*64)
#define ATTN_SMEM_BYTES (ATTN_WORDS * 4)    // 74496

#define C_QK   0.180336880f     // 0.125 * log2(e)
#define C_MASK 14426.950408f    // 10000 * log2(e)

__global__ __launch_bounds__(256, 2) void attn_h(const float* __restrict__ mask)
{
    extern __shared__ uint32_t sm2[];
    uint32_t sbase = smem_u32(sm2);

    int qb = (int)gridDim.x - 1 - (int)blockIdx.x;   // heavy blocks first
    int bh = blockIdx.y;
    int b = bh >> 4, h = bh & 15;

    const __half* Qg = g_q + ((size_t)bh * SS + qb * 128) * HDIM;
    const __half* Kg = g_k + (size_t)bh * SS * HDIM;
    const __half* Vg = g_v + (size_t)bh * HDIM * SS;   // [d][s]
    const float*  Mg = mask + b * SS;

    int tid = threadIdx.x;
    int wid = tid >> 5, lane = tid & 31;
    int lr = lane >> 2, lc = lane & 3;
    int wm = wid * 16;

    // stage Q
    #pragma unroll
    for (int i = 0; i < 4; i++) {
        int c = tid + i * 256;
        int row = c >> 3, w4 = c & 7;
        uint4 t = *(const uint4*)(Qg + row * HDIM + w4 * 8);
        *(uint4*)((char*)sm2 + (QS_OFF + row * KQ + w4 * 4) * 4) = t;
    }

    uint32_t aq = sbase + (QS_OFF + (wm + (lane & 15)) * KQ + ((lane >> 4) << 2)) * 4;
    uint32_t bk[4];
    #pragma unroll
    for (int np = 0; np < 4; np++)
        bk[np] = ((np * 16 + (lane & 7) + ((lane >> 4) << 3)) * KQ + (((lane >> 3) & 1) << 2)) * 4;

    int stgRow[2], stgW4[2];
    #pragma unroll
    for (int i = 0; i < 2; i++) {
        int c = tid + i * 256;
        stgRow[i] = c >> 3; stgW4[i] = c & 7;
    }

    float of[8][4];
    #pragma unroll
    for (int nt = 0; nt < 8; nt++)
        #pragma unroll
        for (int c = 0; c < 4; c++) of[nt][c] = 0.0f;
    float m0 = NEG_BIG, m1 = NEG_BIG, l0 = 0.0f, l1 = 0.0f;

    int row_g0 = qb * 128 + wm + lr;
    int row_g1 = row_g0 + 8;
    int wrow_max = qb * 128 + wm + 15;   // warp's last query row

    int jbmax = 2 * qb + 1;

    // prologue: stages for jb=0,1
    #pragma unroll
    for (int s = 0; s < 2; s++) {
        uint32_t ko = (KS_OFF + s * 64 * KQ) * 4;
        uint32_t vo = (VT_OFF + s * 64 * KQ) * 4;
        int koffs = s * 64;
        #pragma unroll
        for (int i = 0; i < 2; i++) {
            CP_ASYNC16(sbase + ko + (stgRow[i] * KQ + stgW4[i] * 4) * 4,
                       Kg + (size_t)(koffs + stgRow[i]) * HDIM + stgW4[i] * 8);
            CP_ASYNC16(sbase + vo + (stgRow[i] * KQ + stgW4[i] * 4) * 4,
                       Vg + (size_t)stgRow[i] * SS + koffs + stgW4[i] * 8);
        }
        if (tid < 16) CP_ASYNC16(sbase + (MV_OFF + s * 64) * 4 + tid * 16, Mg + koffs + tid * 4);
        CP_COMMIT();
    }

    int stg = 0;
    for (int jb = 0; jb <= jbmax; jb++) {
        CP_WAIT1();
        __syncthreads();

        if (jb + 2 <= jbmax) {
            int ns = stg + 2; if (ns >= ASTG) ns -= ASTG;
            uint32_t ko = (KS_OFF + ns * 64 * KQ) * 4;
            uint32_t vo = (VT_OFF + ns * 64 * KQ) * 4;
            int koffs = (jb + 2) * 64;
            #pragma unroll
            for (int i = 0; i < 2; i++) {
                CP_ASYNC16(sbase + ko + (stgRow[i] * KQ + stgW4[i] * 4) * 4,
                           Kg + (size_t)(koffs + stgRow[i]) * HDIM + stgW4[i] * 8);
                CP_ASYNC16(sbase + vo + (stgRow[i] * KQ + stgW4[i] * 4) * 4,
                           Vg + (size_t)stgRow[i] * SS + koffs + stgW4[i] * 8);
            }
            if (tid < 16) CP_ASYNC16(sbase + (MV_OFF + ns * 64) * 4 + tid * 16,
                                     Mg + koffs + tid * 4);
        }
        CP_COMMIT();

        // warp-uniform skip of fully-masked (causal) chunks
        if (jb * 64 <= wrow_max) {
            uint32_t ksb = sbase + (KS_OFF + stg * 64 * KQ) * 4;
            uint32_t vtb = sbase + (VT_OFF + stg * 64 * KQ) * 4;
            const float* mv = (const float*)(sm2 + MV_OFF + stg * 64);

            // S = Q K^T
            float sf[8][4];
            #pragma unroll
            for (int nt = 0; nt < 8; nt++)
                #pragma unroll
                for (int c = 0; c < 4; c++) sf[nt][c] = 0.0f;

            #pragma unroll
            for (int ks = 0; ks < 4; ks++) {
                uint32_t kb = ks * 32;
                uint32_t a0, a1, a2, a3;
                ldsm4(a0, a1, a2, a3, aq + kb);
                #pragma unroll
                for (int np = 0; np < 4; np++) {
                    uint32_t b0, b1, b2, b3;
                    ldsm4(b0, b1, b2, b3, ksb + bk[np] + kb);
                    mma_f16(sf[2*np][0], sf[2*np][1], sf[2*np][2], sf[2*np][3],
                            a0, a1, a2, a3, b0, b1);
                    mma_f16(sf[2*np+1][0], sf[2*np+1][1], sf[2*np+1][2], sf[2*np+1][3],
                            a0, a1, a2, a3, b2, b3);
                }
            }

            // base-2 domain scores + masks + row max
            float rmax0 = NEG_BIG, rmax1 = NEG_BIG;
            #pragma unroll
            for (int nt = 0; nt < 8; nt++) {
                int cg = jb * 64 + nt * 8 + lc * 2;
                float pma = (mv[nt * 8 + lc * 2]     - 1.0f) * C_MASK;
                float pmb = (mv[nt * 8 + lc * 2 + 1] - 1.0f) * C_MASK;
                float v0 = sf[nt][0] * C_QK + pma; if (cg     > row_g0) v0 = NEG_BIG;
                float v1 = sf[nt][1] * C_QK + pmb; if (cg + 1 > row_g0) v1 = NEG_BIG;
                float v2 = sf[nt][2] * C_QK + pma; if (cg     > row_g1) v2 = NEG_BIG;
                float v3 = sf[nt][3] * C_QK + pmb; if (cg + 1 > row_g1) v3 = NEG_BIG;
                sf[nt][0] = v0; sf[nt][1] = v1; sf[nt][2] = v2; sf[nt][3] = v3;
                rmax0 = fmaxf(rmax0, fmaxf(v0, v1));
                rmax1 = fmaxf(rmax1, fmaxf(v2, v3));
            }
            rmax0 = fmaxf(rmax0, __shfl_xor_sync(0xffffffffu, rmax0, 1));
            rmax0 = fmaxf(rmax0, __shfl_xor_sync(0xffffffffu, rmax0, 2));
            rmax1 = fmaxf(rmax1, __shfl_xor_sync(0xffffffffu, rmax1, 1));
            rmax1 = fmaxf(rmax1, __shfl_xor_sync(0xffffffffu, rmax1, 2));

            float mn0 = fmaxf(m0, rmax0), mn1 = fmaxf(m1, rmax1);
            float sc0 = exp2f(m0 - mn0), sc1 = exp2f(m1 - mn1);
            m0 = mn0; m1 = mn1;

            // 2^(s - m) via f16x2 EX2 -> half2 P = A-fragments directly
            uint32_t ph2[8][2];
            float ls0 = 0.0f, ls1 = 0.0f;
            #pragma unroll
            for (int nt = 0; nt < 8; nt++) {
                uint32_t r0 = ex2_h2(sf[nt][0] - mn0, sf[nt][1] - mn0);
                uint32_t r1 = ex2_h2(sf[nt][2] - mn1, sf[nt][3] - mn1);
                ph2[nt][0] = r0;
                ph2[nt][1] = r1;
                float2 f0 = __half22float2(*(__half2*)&r0);
                float2 f1 = __half22float2(*(__half2*)&r1);
                ls0 += f0.x + f0.y;
                ls1 += f1.x + f1.y;
                of[nt][0] *= sc0; of[nt][1] *= sc0;
                of[nt][2] *= sc1; of[nt][3] *= sc1;
            }
            ls0 += __shfl_xor_sync(0xffffffffu, ls0, 1);
            ls0 += __shfl_xor_sync(0xffffffffu, ls0, 2);
            ls1 += __shfl_xor_sync(0xffffffffu, ls1, 1);
            ls1 += __shfl_xor_sync(0xffffffffu, ls1, 2);
            l0 = l0 * sc0 + ls0;
            l1 = l1 * sc1 + ls1;

            // O += P V   (A = ph2 in registers, B = Vt fragments)
            #pragma unroll
            for (int ks = 0; ks < 4; ks++) {
                uint32_t kb = ks * 32;
                uint32_t a0 = ph2[2*ks][0];
                uint32_t a1 = ph2[2*ks][1];
                uint32_t a2 = ph2[2*ks+1][0];
                uint32_t a3 = ph2[2*ks+1][1];
                #pragma unroll
                for (int np = 0; np < 4; np++) {
                    uint32_t b0, b1, b2, b3;
                    ldsm4(b0, b1, b2, b3, vtb + bk[np] + kb);
                    mma_f16(of[2*np][0], of[2*np][1], of[2*np][2], of[2*np][3],
                            a0, a1, a2, a3, b0, b1);
                    mma_f16(of[2*np+1][0], of[2*np+1][1], of[2*np+1][2], of[2*np+1][3],
                            a0, a1, a2, a3, b2, b3);
                }
            }
        }

        if (++stg >= ASTG) stg = 0;
    }

    float inv0 = 1.0f / l0, inv1 = 1.0f / l1;
    size_t r0w = ((size_t)b * SS + qb * 128 + wm + lr) * DD + h * HDIM;
    size_t r1w = r0w + (size_t)8 * DD;
    #pragma unroll
    for (int nt = 0; nt < 8; nt++) {
        __half2 o0 = __floats2half2_rn(of[nt][0] * inv0, of[nt][1] * inv0);
        __half2 o1 = __floats2half2_rn(of[nt][2] * inv1, of[nt][3] * inv1);
        *(__half2*)(g_ao + r0w + nt * 8 + lc * 2) = o0;
        *(__half2*)(g_ao + r1w + nt * 8 + lc * 2) = o1;
    }
}

// ---------------------------------------------------------------------------
extern "C" void kernel_launch(void* const* d_in, const int* in_sizes, int n_in,
                              void* d_out, int out_size)
{
    const float* x     = (const float*)d_in[0];
    const float* amask = (const float*)d_in[1];
    const float* Wq    = (const float*)d_in[2];
    const float* bq    = (const float*)d_in[3];
    const float* Wk    = (const float*)d_in[4];
    const float* bk    = (const float*)d_in[5];
    const float* Wv    = (const float*)d_in[6];
    const float* bv    = (const float*)d_in[7];
    const float* Wo    = (const float*)d_in[8];
    const float* bo    = (const float*)d_in[9];
    const float* gam   = (const float*)d_in[10];
    const float* bet   = (const float*)d_in[11];
    float* out = (float*)d_out;

    cudaFuncSetAttribute(attn_h,
                         cudaFuncAttributeMaxDynamicSharedMemorySize,
                         ATTN_SMEM_BYTES);
    cudaFuncSetAttribute(gemm_h,
                         cudaFuncAttributeMaxDynamicSharedMemorySize,
                         GEMM_SMEM_BYTES);

    dim3 cvgrid(DD * DD / 4 / 256, 4);   // (1024, 4)
    cvtw_all<<<cvgrid, 256>>>(Wq, Wk, Wv, Wo);
    bias_kernel<<<12, 256>>>(bq, bk, bv);

    ln_kernel<<<MM/8, 256>>>(x, gam, bet);

    dim3 qkvgrid(3*DD/128, MM/128);   // (24, 64)
    gemm_h<<<qkvgrid, 256, GEMM_SMEM_BYTES>>>(0, nullptr, nullptr, nullptr);

    dim3 agrid(SS/128, BB*HH);        // (16, 64)
    attn_h<<<agrid, 256, ATTN_SMEM_BYTES>>>(amask);

    dim3 ogrid(DD/128, MM/128);       // (8, 64)
    gemm_h<<<ogrid, 256, GEMM_SMEM_BYTES>>>(1, bo, x, out);
}